// round 10
// baseline (speedup 1.0000x reference)
#include <cuda_runtime.h>

// Problem constants (fixed by the reference).
constexpr int NN = 100000;   // nodes
constexpr int NE = 1600000;  // edges
constexpr int F1 = 64;       // layer-1 out features (== Fin)
constexpr int F2 = 32;       // layer-2 out features
constexpr int SB = (NN + 1023) / 1024; // 98 scan blocks (1024 threads)
constexpr int PB = NE / 512;           // 3125 prep blocks (128 thr x 4 edges)
constexpr int GB1 = NN / 32;           // 3125 gemm blocks in fused kernel

// Scratch (device globals — referenced ONLY inside device code; passing the
// symbol as a kernel arg from host passes the host shadow address on GB300
// ATS and silently corrupts results — R5/R6 bug).
// g_deg is zero at program load (static init) and re-zeroed by fill_csr at
// the end of EVERY call -> identical state across graph replays.
__device__ int   g_deg[NN];
__device__ int   g_off[NN + 1];
__device__ int   g_cur[NN];
__device__ int   g_bsum[SB];
__device__ int   g_ticket;
__device__ int   g_done;
__device__ int   g_csr_src[NE];
__device__ float g_dinv[NN];
__device__ float g_h1[(size_t)NN * F1];    // raw x@W1 (NOT dinv-scaled)
__device__ float g_hs2[(size_t)NN * F2];   // (h1@W2) * dinv[row]

// ---------------------------------------------------------------------------
// Per-block dtype detect: int64 LE node ids < 2^31 -> ALL odd 32-bit words
// zero. 32 consecutive zero odd-words cannot happen for int32 node ids here.
// Deterministic for a fixed input. Costs one 32-lane gather (L2-hit).
__device__ __forceinline__ int detect_is64_block(const unsigned int* uw,
                                                 int tid, int* shared_flag) {
    if (tid < 32) {
        unsigned v = uw[2 * tid + 1];
        unsigned any = __ballot_sync(0xffffffffu, v != 0u);
        if (tid == 0) *shared_flag = (any == 0u) ? 1 : 0;
    }
    __syncthreads();
    return *shared_flag;
}

// ---------------------------------------------------------------------------
// FUSED: blocks [0, PB) -> edge-degree histogram (4 edges/thread);
// blocks [PB, PB+GB1) -> raw gemm1 (h1 = x @ W1).
__global__ void fused_prep_gemm1(const float* __restrict__ x,
                                 const float* __restrict__ W,
                                 const int* __restrict__ w) {
    constexpr int K = 64, ROWS = 32, XP = K + 4, FOUT = F1;
    constexpr int NT = 128;
    __shared__ float xs[ROWS][XP];
    __shared__ float ws[K][FOUT];

    int tid = threadIdx.x;
    if (blockIdx.x < PB) {
        __shared__ int s_is64;
        int is64 = detect_is64_block((const unsigned int*)w, tid, &s_is64);
        int base = blockIdx.x * 512;
#pragma unroll
        for (int r = 0; r < 4; r++) {
            int e = base + r * 128 + tid;
            int d = is64 ? w[2 * (NE + e)] : w[NE + e];
            atomicAdd(&g_deg[d], 1);
        }
        return;
    }

    // ---- gemm phase: 32 rows, 4x4 micro-tile, raw (unscaled) output ----
    int row0 = (blockIdx.x - PB) * ROWS;
    for (int f4 = tid; f4 < ROWS * K / 4; f4 += NT) {
        int r = f4 >> 4, kc = f4 & 15;
        float4 v = ((const float4*)(x + (size_t)(row0 + r) * K))[kc];
        *(float4*)&xs[r][kc * 4] = v;
    }
    for (int f4 = tid; f4 < K * FOUT / 4; f4 += NT)
        ((float4*)ws)[f4] = ((const float4*)W)[f4];
    __syncthreads();

    int j = tid % 16;
    int i = tid / 16;
    float acc[4][4] = {};
#pragma unroll 8
    for (int k = 0; k < K; k++) {
        float av[4];
#pragma unroll
        for (int r = 0; r < 4; r++) av[r] = xs[i * 4 + r][k];
        float4 b = *(const float4*)&ws[k][j * 4];
#pragma unroll
        for (int r = 0; r < 4; r++) {
            acc[r][0] = fmaf(av[r], b.x, acc[r][0]);
            acc[r][1] = fmaf(av[r], b.y, acc[r][1]);
            acc[r][2] = fmaf(av[r], b.z, acc[r][2]);
            acc[r][3] = fmaf(av[r], b.w, acc[r][3]);
        }
    }
#pragma unroll
    for (int r = 0; r < 4; r++) {
        int row = row0 + i * 4 + r;
        float4 o = make_float4(acc[r][0], acc[r][1], acc[r][2], acc[r][3]);
        *(float4*)&g_h1[(size_t)row * FOUT + j * 4] = o;
    }
}

// ---------------------------------------------------------------------------
// Single-kernel exclusive scan of g_deg -> g_off/g_cur + dinv.
// 98 blocks x 1024 (one block per SM -> all resident; spin is safe).
// Ticket/done counters self-reset for graph replay determinism.
__global__ void scan_all() {
    int i = blockIdx.x * 1024 + threadIdx.x;
    int v = (i < NN) ? g_deg[i] : 0;
    int lane = threadIdx.x & 31, wid = threadIdx.x >> 5;

    // Block-wide inclusive scan of v -> x.
    int x = v;
#pragma unroll
    for (int o = 1; o < 32; o <<= 1) {
        int y = __shfl_up_sync(0xffffffffu, x, o);
        if (lane >= o) x += y;
    }
    __shared__ int ws[32];
    if (lane == 31) ws[wid] = x;
    __syncthreads();
    if (wid == 0) {
        int y = ws[lane];
        int s = y;
#pragma unroll
        for (int o = 1; o < 32; o <<= 1) {
            int z = __shfl_up_sync(0xffffffffu, s, o);
            if (lane >= o) s += z;
        }
        ws[lane] = s - y;  // exclusive warp offsets
        if (lane == 31) ws[31] = s - y;  // keep consistent
    }
    __syncthreads();
    int xin = x + ws[wid];              // block-inclusive scan value
    __shared__ int s_total;
    if (threadIdx.x == 1023) s_total = xin;
    __syncthreads();

    // Publish block total; last-arriving block scans the 98 totals.
    if (threadIdx.x == 0) {
        g_bsum[blockIdx.x] = s_total;
        __threadfence();
        int t = atomicAdd(&g_ticket, 1);
        if (t == SB - 1) {
            int r = 0;
            for (int k = 0; k < SB; k++) {
                int bv = g_bsum[k];
                g_bsum[k] = r;
                r += bv;
            }
            __threadfence();
            atomicExch(&g_ticket, 2 * SB);  // release
        }
        while (((volatile int*)&g_ticket)[0] != 2 * SB) {}
        __threadfence();  // acquire
    }
    __syncthreads();

    int off = g_bsum[blockIdx.x] + xin - v;  // exclusive global offset
    if (i < NN) {
        g_off[i] = off;
        g_cur[i] = off;
        g_dinv[i] = rsqrtf((float)v + 2.0f);  // improved self-loops: +2
        if (i == NN - 1) g_off[NN] = off + v;
    }

    // Self-reset counters for the next (replayed) call.
    __syncthreads();
    if (threadIdx.x == 0) {
        int d2 = atomicAdd(&g_done, 1);
        if (d2 == SB - 1) {
            g_ticket = 0;
            g_done = 0;
        }
    }
}

// ---------------------------------------------------------------------------
// CSR fill (dtype-aware) + re-zero g_deg for the next call (deg is dead now).
__global__ void fill_csr(const int* __restrict__ w) {
    __shared__ int s_is64;
    int tid = threadIdx.x;
    int is64 = detect_is64_block((const unsigned int*)w, tid, &s_is64);
    int e = blockIdx.x * blockDim.x + tid;
    if (e >= NE) return;
    if (e < NN) g_deg[e] = 0;
    int s, d;
    if (is64) {
        s = w[2 * e];
        d = w[2 * (NE + e)];
    } else {
        s = w[e];
        d = w[NE + e];
    }
    int pos = atomicAdd(&g_cur[d], 1);
    g_csr_src[pos] = s;
}

// ---------------------------------------------------------------------------
// Pull aggregation layer 1: one warp per dst node, fused epilogue.
// h1 is RAW: a = sum dinv[s]*h1[s]; out = relu(dv*(a + 2*dv*h_self) + b).
__global__ void agg1(const float* __restrict__ b, float* __restrict__ feat) {
    int warp = (blockIdx.x * 256 + threadIdx.x) >> 5;
    int lane = threadIdx.x & 31;
    if (warp >= NN) return;
    int beg = g_off[warp], end = g_off[warp + 1];
    const float2* __restrict__ hs = (const float2*)g_h1;
    float ax = 0.f, ay = 0.f;
    int i = beg;
    for (; i + 4 <= end; i += 4) {
        int s0 = g_csr_src[i], s1 = g_csr_src[i + 1];
        int s2 = g_csr_src[i + 2], s3 = g_csr_src[i + 3];
        float d0 = g_dinv[s0], d1 = g_dinv[s1];
        float d2 = g_dinv[s2], d3 = g_dinv[s3];
        float2 v0 = hs[s0 * 32 + lane];
        float2 v1 = hs[s1 * 32 + lane];
        float2 v2 = hs[s2 * 32 + lane];
        float2 v3 = hs[s3 * 32 + lane];
        ax = fmaf(d0, v0.x, ax); ay = fmaf(d0, v0.y, ay);
        ax = fmaf(d1, v1.x, ax); ay = fmaf(d1, v1.y, ay);
        ax = fmaf(d2, v2.x, ax); ay = fmaf(d2, v2.y, ay);
        ax = fmaf(d3, v3.x, ax); ay = fmaf(d3, v3.y, ay);
    }
    for (; i < end; i++) {
        int s = g_csr_src[i];
        float d = g_dinv[s];
        float2 v = hs[s * 32 + lane];
        ax = fmaf(d, v.x, ax);
        ay = fmaf(d, v.y, ay);
    }
    float dv = g_dinv[warp];
    float2 h = hs[warp * 32 + lane];
    float2 bb = ((const float2*)b)[lane];
    float tdv = 2.f * dv;
    float2 o;
    o.x = fmaxf(fmaf(dv, fmaf(tdv, h.x, ax), bb.x), 0.f);
    o.y = fmaxf(fmaf(dv, fmaf(tdv, h.y, ay), bb.y), 0.f);
    ((float2*)feat)[warp * 32 + lane] = o;
}

// ---------------------------------------------------------------------------
// GEMM layer 2: g_hs2[row,:] = (x[row,:] @ W) * dinv[row].  K=64, FOUT=32.
__global__ void gemm2_scale(const float* __restrict__ x,
                            const float* __restrict__ W) {
    constexpr int K = 64, ROWS = 32, XP = K + 4, FOUT = F2;
    constexpr int TJ = FOUT / 4;          // 8
    constexpr int NT = (ROWS / 4) * TJ;   // 64 threads
    __shared__ float xs[ROWS][XP];
    __shared__ float ws[K][FOUT];

    int tid = threadIdx.x;
    int row0 = blockIdx.x * ROWS;

    for (int f4 = tid; f4 < ROWS * K / 4; f4 += NT) {
        int r = f4 >> 4, kc = f4 & 15;
        float4 v = ((const float4*)(x + (size_t)(row0 + r) * K))[kc];
        *(float4*)&xs[r][kc * 4] = v;
    }
    for (int f4 = tid; f4 < K * FOUT / 4; f4 += NT)
        ((float4*)ws)[f4] = ((const float4*)W)[f4];
    __syncthreads();

    int j = tid % TJ;
    int i = tid / TJ;
    float acc[4][4] = {};
#pragma unroll 8
    for (int k = 0; k < K; k++) {
        float av[4];
#pragma unroll
        for (int r = 0; r < 4; r++) av[r] = xs[i * 4 + r][k];
        float4 b = *(const float4*)&ws[k][j * 4];
#pragma unroll
        for (int r = 0; r < 4; r++) {
            acc[r][0] = fmaf(av[r], b.x, acc[r][0]);
            acc[r][1] = fmaf(av[r], b.y, acc[r][1]);
            acc[r][2] = fmaf(av[r], b.z, acc[r][2]);
            acc[r][3] = fmaf(av[r], b.w, acc[r][3]);
        }
    }
#pragma unroll
    for (int r = 0; r < 4; r++) {
        int row = row0 + i * 4 + r;
        float dv = g_dinv[row];
        float4 o = make_float4(acc[r][0] * dv, acc[r][1] * dv,
                               acc[r][2] * dv, acc[r][3] * dv);
        *(float4*)&g_hs2[(size_t)row * FOUT + j * 4] = o;
    }
}

// Layer 2: g_hs2 pre-scaled by dinv[row]; each lane owns one float of the row.
__global__ void agg2(const float* __restrict__ b, float* __restrict__ out) {
    int warp = (blockIdx.x * 256 + threadIdx.x) >> 5;
    int lane = threadIdx.x & 31;
    if (warp >= NN) return;
    int beg = g_off[warp], end = g_off[warp + 1];
    const float* __restrict__ hs = g_hs2;
    float a = 0.f;
    int i = beg;
    for (; i + 4 <= end; i += 4) {
        int s0 = g_csr_src[i], s1 = g_csr_src[i + 1];
        int s2 = g_csr_src[i + 2], s3 = g_csr_src[i + 3];
        float v0 = hs[s0 * 32 + lane];
        float v1 = hs[s1 * 32 + lane];
        float v2 = hs[s2 * 32 + lane];
        float v3 = hs[s3 * 32 + lane];
        a += (v0 + v1) + (v2 + v3);
    }
    for (; i < end; i++) a += hs[g_csr_src[i] * 32 + lane];
    float dv = g_dinv[warp];
    float h = hs[warp * 32 + lane];
    out[warp * 32 + lane] = fmaf(dv, fmaf(2.f, h, a), b[lane]);
}

// ---------------------------------------------------------------------------
extern "C" void kernel_launch(void* const* d_in, const int* in_sizes, int n_in,
                              void* d_out, int out_size) {
    const float* x  = (const float*)d_in[0];
    const int*   ei = (const int*)d_in[1];
    const float* W1 = (const float*)d_in[2];
    const float* b1 = (const float*)d_in[3];
    const float* W2 = (const float*)d_in[4];
    const float* b2 = (const float*)d_in[5];

    float* out  = (float*)d_out;              // [N, 32]
    float* feat = out + (size_t)NN * F2;      // [N, 64] feature_map

    // 6 launches total.
    fused_prep_gemm1<<<PB + GB1, 128>>>(x, W1, ei);
    scan_all<<<SB, 1024>>>();
    fill_csr<<<(NE + 255) / 256, 256>>>(ei);
    agg1<<<(NN * 32 + 255) / 256, 256>>>(b1, feat);
    gemm2_scale<<<NN / 32, 64>>>(feat, W2);
    agg2<<<(NN * 32 + 255) / 256, 256>>>(b2, out);
}

// round 11
// speedup vs baseline: 1.0266x; 1.0266x over previous
#include <cuda_runtime.h>
#include <cuda_fp16.h>

// Problem constants (fixed by the reference).
constexpr int NN = 100000;   // nodes
constexpr int NE = 1600000;  // edges
constexpr int F1 = 64;       // layer-1 out features (== Fin)
constexpr int F2 = 32;       // layer-2 out features
constexpr int SB = (NN + 1023) / 1024; // 98 scan blocks (1024 threads)
constexpr int PB = NE / 512;           // 3125 prep blocks (128 thr x 4 edges)
constexpr int GB1 = NN / 32;           // 3125 gemm blocks in fused kernel

// Scratch (device globals — referenced ONLY inside device code; passing the
// symbol as a kernel arg from host passes the host shadow address on GB300
// ATS and silently corrupts results — R5/R6 bug).
// g_deg is zero at program load and re-zeroed by fill_csr every call.
__device__ int    g_deg[NN];
__device__ int    g_off[NN + 1];
__device__ int    g_cur[NN];
__device__ int    g_bsum[SB];
__device__ int    g_ticket;
__device__ int    g_done;
__device__ int    g_csr_src[NE];
__device__ float  g_dinv[NN];
__device__ __half g_h1h[(size_t)NN * F1];   // raw x@W1, fp16 (gather array)
__device__ __half g_hs2h[(size_t)NN * F2];  // (h1@W2)*dinv, fp16 (gather array)

// ---------------------------------------------------------------------------
// Per-block dtype detect: int64 LE node ids < 2^31 -> ALL odd 32-bit words
// zero over the first 32 entries; impossible for int32 node ids here.
__device__ __forceinline__ int detect_is64_block(const unsigned int* uw,
                                                 int tid, int* shared_flag) {
    if (tid < 32) {
        unsigned v = uw[2 * tid + 1];
        unsigned any = __ballot_sync(0xffffffffu, v != 0u);
        if (tid == 0) *shared_flag = (any == 0u) ? 1 : 0;
    }
    __syncthreads();
    return *shared_flag;
}

// ---------------------------------------------------------------------------
// FUSED: blocks [0, PB) -> edge-degree histogram (4 edges/thread);
// blocks [PB, PB+GB1) -> raw gemm1 (h1 = x @ W1, fp32 math, fp16 store).
__global__ void fused_prep_gemm1(const float* __restrict__ x,
                                 const float* __restrict__ W,
                                 const int* __restrict__ w) {
    constexpr int K = 64, ROWS = 32, XP = K + 4, FOUT = F1;
    constexpr int NT = 128;
    __shared__ float xs[ROWS][XP];
    __shared__ float ws[K][FOUT];

    int tid = threadIdx.x;
    if (blockIdx.x < PB) {
        __shared__ int s_is64;
        int is64 = detect_is64_block((const unsigned int*)w, tid, &s_is64);
        int base = blockIdx.x * 512;
#pragma unroll
        for (int r = 0; r < 4; r++) {
            int e = base + r * 128 + tid;
            int d = is64 ? w[2 * (NE + e)] : w[NE + e];
            atomicAdd(&g_deg[d], 1);
        }
        return;
    }

    // ---- gemm phase: 32 rows, 4x4 micro-tile ----
    int row0 = (blockIdx.x - PB) * ROWS;
    for (int f4 = tid; f4 < ROWS * K / 4; f4 += NT) {
        int r = f4 >> 4, kc = f4 & 15;
        float4 v = ((const float4*)(x + (size_t)(row0 + r) * K))[kc];
        *(float4*)&xs[r][kc * 4] = v;
    }
    for (int f4 = tid; f4 < K * FOUT / 4; f4 += NT)
        ((float4*)ws)[f4] = ((const float4*)W)[f4];
    __syncthreads();

    int j = tid % 16;
    int i = tid / 16;
    float acc[4][4] = {};
#pragma unroll 8
    for (int k = 0; k < K; k++) {
        float av[4];
#pragma unroll
        for (int r = 0; r < 4; r++) av[r] = xs[i * 4 + r][k];
        float4 b = *(const float4*)&ws[k][j * 4];
#pragma unroll
        for (int r = 0; r < 4; r++) {
            acc[r][0] = fmaf(av[r], b.x, acc[r][0]);
            acc[r][1] = fmaf(av[r], b.y, acc[r][1]);
            acc[r][2] = fmaf(av[r], b.z, acc[r][2]);
            acc[r][3] = fmaf(av[r], b.w, acc[r][3]);
        }
    }
#pragma unroll
    for (int r = 0; r < 4; r++) {
        int row = row0 + i * 4 + r;
        __half2 p0 = __float22half2_rn(make_float2(acc[r][0], acc[r][1]));
        __half2 p1 = __float22half2_rn(make_float2(acc[r][2], acc[r][3]));
        __half2 pk[2] = {p0, p1};
        *(uint2*)&g_h1h[(size_t)row * FOUT + j * 4] = *(uint2*)pk;
    }
}

// ---------------------------------------------------------------------------
// Single-kernel exclusive scan of g_deg -> g_off/g_cur + dinv.
// 98 blocks x 1024 (<=1 block/SM -> all resident; spin is safe).
__global__ void scan_all() {
    int i = blockIdx.x * 1024 + threadIdx.x;
    int v = (i < NN) ? g_deg[i] : 0;
    int lane = threadIdx.x & 31, wid = threadIdx.x >> 5;

    int x = v;
#pragma unroll
    for (int o = 1; o < 32; o <<= 1) {
        int y = __shfl_up_sync(0xffffffffu, x, o);
        if (lane >= o) x += y;
    }
    __shared__ int ws[32];
    if (lane == 31) ws[wid] = x;
    __syncthreads();
    if (wid == 0) {
        int y = ws[lane];
        int s = y;
#pragma unroll
        for (int o = 1; o < 32; o <<= 1) {
            int z = __shfl_up_sync(0xffffffffu, s, o);
            if (lane >= o) s += z;
        }
        ws[lane] = s - y;  // exclusive warp offsets
    }
    __syncthreads();
    int xin = x + ws[wid];
    __shared__ int s_total;
    if (threadIdx.x == 1023) s_total = xin;
    __syncthreads();

    if (threadIdx.x == 0) {
        g_bsum[blockIdx.x] = s_total;
        __threadfence();
        int t = atomicAdd(&g_ticket, 1);
        if (t == SB - 1) {
            int r = 0;
            for (int k = 0; k < SB; k++) {
                int bv = g_bsum[k];
                g_bsum[k] = r;
                r += bv;
            }
            __threadfence();
            atomicExch(&g_ticket, 2 * SB);  // release
        }
        while (((volatile int*)&g_ticket)[0] != 2 * SB) {}
        __threadfence();  // acquire
    }
    __syncthreads();

    int off = g_bsum[blockIdx.x] + xin - v;
    if (i < NN) {
        g_off[i] = off;
        g_cur[i] = off;
        g_dinv[i] = rsqrtf((float)v + 2.0f);  // improved self-loops: +2
        if (i == NN - 1) g_off[NN] = off + v;
    }

    __syncthreads();
    if (threadIdx.x == 0) {
        int d2 = atomicAdd(&g_done, 1);
        if (d2 == SB - 1) {
            g_ticket = 0;
            g_done = 0;
        }
    }
}

// ---------------------------------------------------------------------------
// CSR fill (dtype-aware) + re-zero g_deg for the next call.
__global__ void fill_csr(const int* __restrict__ w) {
    __shared__ int s_is64;
    int tid = threadIdx.x;
    int is64 = detect_is64_block((const unsigned int*)w, tid, &s_is64);
    int e = blockIdx.x * blockDim.x + tid;
    if (e >= NE) return;
    if (e < NN) g_deg[e] = 0;
    int s, d;
    if (is64) {
        s = w[2 * e];
        d = w[2 * (NE + e)];
    } else {
        s = w[e];
        d = w[NE + e];
    }
    int pos = atomicAdd(&g_cur[d], 1);
    g_csr_src[pos] = s;
}

// ---------------------------------------------------------------------------
// Pull aggregation layer 1: one warp per dst node. Gathers fp16 h1 rows
// (128B/row), accumulates fp32: a = sum dinv[s]*h1[s];
// out = relu(dv*(a + 2*dv*h_self) + b)  -> feature_map (fp32).
__global__ void agg1(const float* __restrict__ b, float* __restrict__ feat) {
    int warp = (blockIdx.x * 256 + threadIdx.x) >> 5;
    int lane = threadIdx.x & 31;
    if (warp >= NN) return;
    int beg = g_off[warp], end = g_off[warp + 1];
    const __half2* __restrict__ hs = (const __half2*)g_h1h;
    float ax = 0.f, ay = 0.f;
    int i = beg;
    for (; i + 4 <= end; i += 4) {
        int s0 = g_csr_src[i], s1 = g_csr_src[i + 1];
        int s2 = g_csr_src[i + 2], s3 = g_csr_src[i + 3];
        float d0 = g_dinv[s0], d1 = g_dinv[s1];
        float d2 = g_dinv[s2], d3 = g_dinv[s3];
        float2 v0 = __half22float2(hs[s0 * 32 + lane]);
        float2 v1 = __half22float2(hs[s1 * 32 + lane]);
        float2 v2 = __half22float2(hs[s2 * 32 + lane]);
        float2 v3 = __half22float2(hs[s3 * 32 + lane]);
        ax = fmaf(d0, v0.x, ax); ay = fmaf(d0, v0.y, ay);
        ax = fmaf(d1, v1.x, ax); ay = fmaf(d1, v1.y, ay);
        ax = fmaf(d2, v2.x, ax); ay = fmaf(d2, v2.y, ay);
        ax = fmaf(d3, v3.x, ax); ay = fmaf(d3, v3.y, ay);
    }
    for (; i < end; i++) {
        int s = g_csr_src[i];
        float d = g_dinv[s];
        float2 v = __half22float2(hs[s * 32 + lane]);
        ax = fmaf(d, v.x, ax);
        ay = fmaf(d, v.y, ay);
    }
    float dv = g_dinv[warp];
    float2 h = __half22float2(hs[warp * 32 + lane]);
    float2 bb = ((const float2*)b)[lane];
    float tdv = 2.f * dv;
    float2 o;
    o.x = fmaxf(fmaf(dv, fmaf(tdv, h.x, ax), bb.x), 0.f);
    o.y = fmaxf(fmaf(dv, fmaf(tdv, h.y, ay), bb.y), 0.f);
    ((float2*)feat)[warp * 32 + lane] = o;
}

// ---------------------------------------------------------------------------
// GEMM layer 2: g_hs2h[row,:] = half((feat[row,:] @ W) * dinv[row]).
__global__ void gemm2_scale(const float* __restrict__ x,
                            const float* __restrict__ W) {
    constexpr int K = 64, ROWS = 32, XP = K + 4, FOUT = F2;
    constexpr int TJ = FOUT / 4;          // 8
    constexpr int NT = (ROWS / 4) * TJ;   // 64 threads
    __shared__ float xs[ROWS][XP];
    __shared__ float ws[K][FOUT];

    int tid = threadIdx.x;
    int row0 = blockIdx.x * ROWS;

    for (int f4 = tid; f4 < ROWS * K / 4; f4 += NT) {
        int r = f4 >> 4, kc = f4 & 15;
        float4 v = ((const float4*)(x + (size_t)(row0 + r) * K))[kc];
        *(float4*)&xs[r][kc * 4] = v;
    }
    for (int f4 = tid; f4 < K * FOUT / 4; f4 += NT)
        ((float4*)ws)[f4] = ((const float4*)W)[f4];
    __syncthreads();

    int j = tid % TJ;
    int i = tid / TJ;
    float acc[4][4] = {};
#pragma unroll 8
    for (int k = 0; k < K; k++) {
        float av[4];
#pragma unroll
        for (int r = 0; r < 4; r++) av[r] = xs[i * 4 + r][k];
        float4 b = *(const float4*)&ws[k][j * 4];
#pragma unroll
        for (int r = 0; r < 4; r++) {
            acc[r][0] = fmaf(av[r], b.x, acc[r][0]);
            acc[r][1] = fmaf(av[r], b.y, acc[r][1]);
            acc[r][2] = fmaf(av[r], b.z, acc[r][2]);
            acc[r][3] = fmaf(av[r], b.w, acc[r][3]);
        }
    }
#pragma unroll
    for (int r = 0; r < 4; r++) {
        int row = row0 + i * 4 + r;
        float dv = g_dinv[row];
        __half2 p0 = __float22half2_rn(make_float2(acc[r][0] * dv, acc[r][1] * dv));
        __half2 p1 = __float22half2_rn(make_float2(acc[r][2] * dv, acc[r][3] * dv));
        __half2 pk[2] = {p0, p1};
        *(uint2*)&g_hs2h[(size_t)row * FOUT + j * 4] = *(uint2*)pk;
    }
}

// Layer 2: hs2 (fp16, pre-scaled by dinv[row]); lane owns one feature.
__global__ void agg2(const float* __restrict__ b, float* __restrict__ out) {
    int warp = (blockIdx.x * 256 + threadIdx.x) >> 5;
    int lane = threadIdx.x & 31;
    if (warp >= NN) return;
    int beg = g_off[warp], end = g_off[warp + 1];
    const __half* __restrict__ hs = g_hs2h;
    float a = 0.f;
    int i = beg;
    for (; i + 4 <= end; i += 4) {
        int s0 = g_csr_src[i], s1 = g_csr_src[i + 1];
        int s2 = g_csr_src[i + 2], s3 = g_csr_src[i + 3];
        float v0 = __half2float(hs[s0 * 32 + lane]);
        float v1 = __half2float(hs[s1 * 32 + lane]);
        float v2 = __half2float(hs[s2 * 32 + lane]);
        float v3 = __half2float(hs[s3 * 32 + lane]);
        a += (v0 + v1) + (v2 + v3);
    }
    for (; i < end; i++) a += __half2float(hs[g_csr_src[i] * 32 + lane]);
    float dv = g_dinv[warp];
    float h = __half2float(hs[warp * 32 + lane]);
    out[warp * 32 + lane] = fmaf(dv, fmaf(2.f, h, a), b[lane]);
}

// ---------------------------------------------------------------------------
extern "C" void kernel_launch(void* const* d_in, const int* in_sizes, int n_in,
                              void* d_out, int out_size) {
    const float* x  = (const float*)d_in[0];
    const int*   ei = (const int*)d_in[1];
    const float* W1 = (const float*)d_in[2];
    const float* b1 = (const float*)d_in[3];
    const float* W2 = (const float*)d_in[4];
    const float* b2 = (const float*)d_in[5];

    float* out  = (float*)d_out;              // [N, 32]
    float* feat = out + (size_t)NN * F2;      // [N, 64] feature_map

    fused_prep_gemm1<<<PB + GB1, 128>>>(x, W1, ei);
    scan_all<<<SB, 1024>>>();
    fill_csr<<<(NE + 255) / 256, 256>>>(ei);
    agg1<<<(NN * 32 + 255) / 256, 256>>>(b1, feat);
    gemm2_scale<<<NN / 32, 64>>>(feat, W2);
    agg2<<<(NN * 32 + 255) / 256, 256>>>(b2, out);
}

// round 12
// speedup vs baseline: 1.1118x; 1.0830x over previous
#include <cuda_runtime.h>
#include <cuda_fp16.h>

// Problem constants (fixed by the reference).
constexpr int NN = 100000;   // nodes
constexpr int NE = 1600000;  // edges
constexpr int F1 = 64;       // layer-1 out features (== Fin)
constexpr int F2 = 32;       // layer-2 out features
constexpr int SB = (NN + 1023) / 1024;   // 98 scan blocks (1024 threads)
constexpr int PB = NE / 512;             // 3125 prep blocks (128 thr x 4 edges)
constexpr int GB1 = NN / 32;             // 3125 gemm blocks in fused kernel
constexpr int FB = (NE + 255) / 256;     // 6250 csr-fill blocks
constexpr int SCB = (NN * F1 / 2) / (256 * 4);  // 3125 h1-scale blocks

// Scratch (device globals — referenced ONLY inside device code; passing the
// symbol as a kernel arg from host passes the host shadow address on GB300
// ATS and silently corrupts results — R5/R6 bug).
// g_deg is zero at program load and re-zeroed by fill_csr every call.
__device__ int    g_deg[NN];
__device__ int    g_off[NN + 1];
__device__ int    g_cur[NN];
__device__ int    g_bsum[SB];
__device__ int    g_ticket;
__device__ int    g_done;
__device__ int    g_csr_src[NE];
__device__ float  g_dinv[NN];
__device__ __half g_h1h[(size_t)NN * F1];   // x@W1; scaled by dinv in-place later
__device__ __half g_hs2h[(size_t)NN * F2];  // (h1@W2)*dinv, fp16

// ---------------------------------------------------------------------------
// Per-block dtype detect: int64 LE node ids < 2^31 -> ALL odd 32-bit words
// zero over the first 32 entries; impossible for int32 node ids here.
__device__ __forceinline__ int detect_is64_block(const unsigned int* uw,
                                                 int tid, int* shared_flag) {
    if (tid < 32) {
        unsigned v = uw[2 * tid + 1];
        unsigned any = __ballot_sync(0xffffffffu, v != 0u);
        if (tid == 0) *shared_flag = (any == 0u) ? 1 : 0;
    }
    __syncthreads();
    return *shared_flag;
}

// ---------------------------------------------------------------------------
// FUSED: blocks [0, PB) -> edge-degree histogram (4 edges/thread);
// blocks [PB, PB+GB1) -> raw gemm1 (h1 = x @ W1, fp32 math, fp16 store).
__global__ void fused_prep_gemm1(const float* __restrict__ x,
                                 const float* __restrict__ W,
                                 const int* __restrict__ w) {
    constexpr int K = 64, ROWS = 32, XP = K + 4, FOUT = F1;
    constexpr int NT = 128;
    __shared__ float xs[ROWS][XP];
    __shared__ float ws[K][FOUT];

    int tid = threadIdx.x;
    if (blockIdx.x < PB) {
        __shared__ int s_is64;
        int is64 = detect_is64_block((const unsigned int*)w, tid, &s_is64);
        int base = blockIdx.x * 512;
#pragma unroll
        for (int r = 0; r < 4; r++) {
            int e = base + r * 128 + tid;
            int d = is64 ? w[2 * (NE + e)] : w[NE + e];
            atomicAdd(&g_deg[d], 1);
        }
        return;
    }

    // ---- gemm phase: 32 rows, 4x4 micro-tile ----
    int row0 = (blockIdx.x - PB) * ROWS;
    for (int f4 = tid; f4 < ROWS * K / 4; f4 += NT) {
        int r = f4 >> 4, kc = f4 & 15;
        float4 v = ((const float4*)(x + (size_t)(row0 + r) * K))[kc];
        *(float4*)&xs[r][kc * 4] = v;
    }
    for (int f4 = tid; f4 < K * FOUT / 4; f4 += NT)
        ((float4*)ws)[f4] = ((const float4*)W)[f4];
    __syncthreads();

    int j = tid % 16;
    int i = tid / 16;
    float acc[4][4] = {};
#pragma unroll 8
    for (int k = 0; k < K; k++) {
        float av[4];
#pragma unroll
        for (int r = 0; r < 4; r++) av[r] = xs[i * 4 + r][k];
        float4 b = *(const float4*)&ws[k][j * 4];
#pragma unroll
        for (int r = 0; r < 4; r++) {
            acc[r][0] = fmaf(av[r], b.x, acc[r][0]);
            acc[r][1] = fmaf(av[r], b.y, acc[r][1]);
            acc[r][2] = fmaf(av[r], b.z, acc[r][2]);
            acc[r][3] = fmaf(av[r], b.w, acc[r][3]);
        }
    }
#pragma unroll
    for (int r = 0; r < 4; r++) {
        int row = row0 + i * 4 + r;
        __half2 p0 = __float22half2_rn(make_float2(acc[r][0], acc[r][1]));
        __half2 p1 = __float22half2_rn(make_float2(acc[r][2], acc[r][3]));
        __half2 pk[2] = {p0, p1};
        *(uint2*)&g_h1h[(size_t)row * FOUT + j * 4] = *(uint2*)pk;
    }
}

// ---------------------------------------------------------------------------
// Single-kernel exclusive scan of g_deg -> g_off/g_cur + dinv.
// 98 blocks x 1024 (<=1 block/SM -> all resident; spin is safe).
__global__ void scan_all() {
    int i = blockIdx.x * 1024 + threadIdx.x;
    int v = (i < NN) ? g_deg[i] : 0;
    int lane = threadIdx.x & 31, wid = threadIdx.x >> 5;

    int x = v;
#pragma unroll
    for (int o = 1; o < 32; o <<= 1) {
        int y = __shfl_up_sync(0xffffffffu, x, o);
        if (lane >= o) x += y;
    }
    __shared__ int ws[32];
    if (lane == 31) ws[wid] = x;
    __syncthreads();
    if (wid == 0) {
        int y = ws[lane];
        int s = y;
#pragma unroll
        for (int o = 1; o < 32; o <<= 1) {
            int z = __shfl_up_sync(0xffffffffu, s, o);
            if (lane >= o) s += z;
        }
        ws[lane] = s - y;  // exclusive warp offsets
    }
    __syncthreads();
    int xin = x + ws[wid];
    __shared__ int s_total;
    if (threadIdx.x == 1023) s_total = xin;
    __syncthreads();

    if (threadIdx.x == 0) {
        g_bsum[blockIdx.x] = s_total;
        __threadfence();
        int t = atomicAdd(&g_ticket, 1);
        if (t == SB - 1) {
            int r = 0;
            for (int k = 0; k < SB; k++) {
                int bv = g_bsum[k];
                g_bsum[k] = r;
                r += bv;
            }
            __threadfence();
            atomicExch(&g_ticket, 2 * SB);  // release
        }
        while (((volatile int*)&g_ticket)[0] != 2 * SB) {}
        __threadfence();  // acquire
    }
    __syncthreads();

    int off = g_bsum[blockIdx.x] + xin - v;
    if (i < NN) {
        g_off[i] = off;
        g_cur[i] = off;
        g_dinv[i] = rsqrtf((float)v + 2.0f);  // improved self-loops: +2
        if (i == NN - 1) g_off[NN] = off + v;
    }

    __syncthreads();
    if (threadIdx.x == 0) {
        int d2 = atomicAdd(&g_done, 1);
        if (d2 == SB - 1) {
            g_ticket = 0;
            g_done = 0;
        }
    }
}

// ---------------------------------------------------------------------------
// FUSED: blocks [0, FB) -> CSR fill (dtype-aware) + re-zero g_deg;
// blocks [FB, FB+SCB) -> scale h1h in-place by dinv[row] (fp32 math).
// Each scale thread handles 4 consecutive half2 (16B, row-aligned: 32 h2/row).
__global__ void fill_csr_scale(const int* __restrict__ w) {
    int tid = threadIdx.x;
    if (blockIdx.x >= FB) {
        int h2i = ((blockIdx.x - FB) * 256 + tid) * 4;   // half2 index
        int row = h2i >> 5;
        float dv = g_dinv[row];
        uint2* p = (uint2*)&g_h1h[(size_t)h2i * 2];
        uint2 v0 = p[0], v1 = p[1];
        __half2* h = (__half2*)&v0;
        __half2* h2 = (__half2*)&v1;
#pragma unroll
        for (int k = 0; k < 2; k++) {
            float2 f = __half22float2(h[k]);
            h[k] = __float22half2_rn(make_float2(f.x * dv, f.y * dv));
            float2 g = __half22float2(h2[k]);
            h2[k] = __float22half2_rn(make_float2(g.x * dv, g.y * dv));
        }
        p[0] = v0;
        p[1] = v1;
        return;
    }
    __shared__ int s_is64;
    int is64 = detect_is64_block((const unsigned int*)w, tid, &s_is64);
    int e = blockIdx.x * 256 + tid;
    if (e >= NE) return;
    if (e < NN) g_deg[e] = 0;
    int s, d;
    if (is64) {
        s = w[2 * e];
        d = w[2 * (NE + e)];
    } else {
        s = w[e];
        d = w[NE + e];
    }
    int pos = atomicAdd(&g_cur[d], 1);
    g_csr_src[pos] = s;
}

// ---------------------------------------------------------------------------
// Pull aggregation layer 1. One warp per dst node; TWO edges in flight via
// 16-lane half-warps. hs1 rows are PRE-SCALED by dinv[src] (fp16, 128B/row);
// lane l of group g owns features [4l, 4l+4) as a uint2 (half4) gather.
// out = relu(dv*(sum + 2*hs_self) + b) -> feature_map (fp32).
__global__ void agg1(const float* __restrict__ b, float* __restrict__ feat) {
    int warp = (blockIdx.x * 256 + threadIdx.x) >> 5;
    int lane = threadIdx.x & 31;
    if (warp >= NN) return;
    int g = lane >> 4, l = lane & 15;
    int beg = g_off[warp], end = g_off[warp + 1];
    const uint2* __restrict__ hs = (const uint2*)g_h1h;  // 16 uint2 per row
    const int* __restrict__ csr = g_csr_src;

    float a0 = 0.f, a1 = 0.f, a2 = 0.f, a3 = 0.f;
    int i = beg + g;
    // unroll x2: this half-warp handles edges i, i+2 (stride 2 per group).
    for (; i + 2 < end; i += 4) {
        int s0 = csr[i];
        int s1 = csr[i + 2];
        uint2 v0 = hs[s0 * 16 + l];
        uint2 v1 = hs[s1 * 16 + l];
        float2 f00 = __half22float2(*(__half2*)&v0.x);
        float2 f01 = __half22float2(*(__half2*)&v0.y);
        float2 f10 = __half22float2(*(__half2*)&v1.x);
        float2 f11 = __half22float2(*(__half2*)&v1.y);
        a0 += f00.x + f10.x;
        a1 += f00.y + f10.y;
        a2 += f01.x + f11.x;
        a3 += f01.y + f11.y;
    }
    if (i < end) {
        int s0 = csr[i];
        uint2 v0 = hs[s0 * 16 + l];
        float2 f00 = __half22float2(*(__half2*)&v0.x);
        float2 f01 = __half22float2(*(__half2*)&v0.y);
        a0 += f00.x;
        a1 += f00.y;
        a2 += f01.x;
        a3 += f01.y;
    }
    // combine the two half-warps (same features, disjoint edges).
    a0 += __shfl_xor_sync(0xffffffffu, a0, 16);
    a1 += __shfl_xor_sync(0xffffffffu, a1, 16);
    a2 += __shfl_xor_sync(0xffffffffu, a2, 16);
    a3 += __shfl_xor_sync(0xffffffffu, a3, 16);

    if (g == 0) {
        float dv = g_dinv[warp];
        uint2 hv = hs[warp * 16 + l];
        float2 h0 = __half22float2(*(__half2*)&hv.x);
        float2 h1 = __half22float2(*(__half2*)&hv.y);
        float4 bb = ((const float4*)b)[l];
        float4 o;
        o.x = fmaxf(fmaf(dv, fmaf(2.f, h0.x, a0), bb.x), 0.f);
        o.y = fmaxf(fmaf(dv, fmaf(2.f, h0.y, a1), bb.y), 0.f);
        o.z = fmaxf(fmaf(dv, fmaf(2.f, h1.x, a2), bb.z), 0.f);
        o.w = fmaxf(fmaf(dv, fmaf(2.f, h1.y, a3), bb.w), 0.f);
        ((float4*)feat)[warp * 16 + l] = o;
    }
}

// ---------------------------------------------------------------------------
// GEMM layer 2: g_hs2h[row,:] = half((feat[row,:] @ W) * dinv[row]).
__global__ void gemm2_scale(const float* __restrict__ x,
                            const float* __restrict__ W) {
    constexpr int K = 64, ROWS = 32, XP = K + 4, FOUT = F2;
    constexpr int TJ = FOUT / 4;          // 8
    constexpr int NT = (ROWS / 4) * TJ;   // 64 threads
    __shared__ float xs[ROWS][XP];
    __shared__ float ws[K][FOUT];

    int tid = threadIdx.x;
    int row0 = blockIdx.x * ROWS;

    for (int f4 = tid; f4 < ROWS * K / 4; f4 += NT) {
        int r = f4 >> 4, kc = f4 & 15;
        float4 v = ((const float4*)(x + (size_t)(row0 + r) * K))[kc];
        *(float4*)&xs[r][kc * 4] = v;
    }
    for (int f4 = tid; f4 < K * FOUT / 4; f4 += NT)
        ((float4*)ws)[f4] = ((const float4*)W)[f4];
    __syncthreads();

    int j = tid % TJ;
    int i = tid / TJ;
    float acc[4][4] = {};
#pragma unroll 8
    for (int k = 0; k < K; k++) {
        float av[4];
#pragma unroll
        for (int r = 0; r < 4; r++) av[r] = xs[i * 4 + r][k];
        float4 b = *(const float4*)&ws[k][j * 4];
#pragma unroll
        for (int r = 0; r < 4; r++) {
            acc[r][0] = fmaf(av[r], b.x, acc[r][0]);
            acc[r][1] = fmaf(av[r], b.y, acc[r][1]);
            acc[r][2] = fmaf(av[r], b.z, acc[r][2]);
            acc[r][3] = fmaf(av[r], b.w, acc[r][3]);
        }
    }
#pragma unroll
    for (int r = 0; r < 4; r++) {
        int row = row0 + i * 4 + r;
        float dv = g_dinv[row];
        __half2 p0 = __float22half2_rn(make_float2(acc[r][0] * dv, acc[r][1] * dv));
        __half2 p1 = __float22half2_rn(make_float2(acc[r][2] * dv, acc[r][3] * dv));
        __half2 pk[2] = {p0, p1};
        *(uint2*)&g_hs2h[(size_t)row * FOUT + j * 4] = *(uint2*)pk;
    }
}

// ---------------------------------------------------------------------------
// Layer-2 aggregation: same 2-edges-per-warp scheme. Row = 32 half = 16 half2;
// lane l owns features [2l, 2l+2) as one half2 (4B).
__global__ void agg2(const float* __restrict__ b, float* __restrict__ out) {
    int warp = (blockIdx.x * 256 + threadIdx.x) >> 5;
    int lane = threadIdx.x & 31;
    if (warp >= NN) return;
    int g = lane >> 4, l = lane & 15;
    int beg = g_off[warp], end = g_off[warp + 1];
    const __half2* __restrict__ hs = (const __half2*)g_hs2h;  // 16 h2 per row
    const int* __restrict__ csr = g_csr_src;

    float a0 = 0.f, a1 = 0.f;
    int i = beg + g;
    for (; i + 2 < end; i += 4) {
        int s0 = csr[i];
        int s1 = csr[i + 2];
        float2 f0 = __half22float2(hs[s0 * 16 + l]);
        float2 f1 = __half22float2(hs[s1 * 16 + l]);
        a0 += f0.x + f1.x;
        a1 += f0.y + f1.y;
    }
    if (i < end) {
        float2 f0 = __half22float2(hs[csr[i] * 16 + l]);
        a0 += f0.x;
        a1 += f0.y;
    }
    a0 += __shfl_xor_sync(0xffffffffu, a0, 16);
    a1 += __shfl_xor_sync(0xffffffffu, a1, 16);

    if (g == 0) {
        float dv = g_dinv[warp];
        float2 h = __half22float2(hs[warp * 16 + l]);
        float2 bb = ((const float2*)b)[l];
        float2 o;
        o.x = fmaf(dv, fmaf(2.f, h.x, a0), bb.x);
        o.y = fmaf(dv, fmaf(2.f, h.y, a1), bb.y);
        ((float2*)out)[warp * 16 + l] = o;
    }
}

// ---------------------------------------------------------------------------
extern "C" void kernel_launch(void* const* d_in, const int* in_sizes, int n_in,
                              void* d_out, int out_size) {
    const float* x  = (const float*)d_in[0];
    const int*   ei = (const int*)d_in[1];
    const float* W1 = (const float*)d_in[2];
    const float* b1 = (const float*)d_in[3];
    const float* W2 = (const float*)d_in[4];
    const float* b2 = (const float*)d_in[5];

    float* out  = (float*)d_out;              // [N, 32]
    float* feat = out + (size_t)NN * F2;      // [N, 64] feature_map

    fused_prep_gemm1<<<PB + GB1, 128>>>(x, W1, ei);
    scan_all<<<SB, 1024>>>();
    fill_csr_scale<<<FB + SCB, 256>>>(ei);
    agg1<<<(NN * 32 + 255) / 256, 256>>>(b1, feat);
    gemm2_scale<<<NN / 32, 64>>>(feat, W2);
    agg2<<<(NN * 32 + 255) / 256, 256>>>(b2, out);
}

// round 13
// speedup vs baseline: 1.1130x; 1.0011x over previous
#include <cuda_runtime.h>
#include <cuda_fp16.h>

// Problem constants (fixed by the reference).
constexpr int NN = 100000;   // nodes
constexpr int NE = 1600000;  // edges
constexpr int F1 = 64;       // layer-1 out features (== Fin)
constexpr int F2 = 32;       // layer-2 out features
constexpr int SB = (NN + 1023) / 1024;   // 98 scan blocks (1024 threads)
constexpr int PB = NE / 512;             // 3125 prep blocks (128 thr x 4 edges)
constexpr int GB1 = NN / 32;             // 3125 gemm blocks in fused kernel
constexpr int FB = (NE + 255) / 256;     // 6250 csr-fill blocks
constexpr int SCB = (NN * F1 / 2) / (256 * 4);  // 3125 h1-scale blocks

// Scratch (device globals — referenced ONLY inside device code; passing the
// symbol as a kernel arg from host passes the host shadow address on GB300
// ATS and silently corrupts results — R5/R6 bug).
// g_deg is zero at program load and re-zeroed by fill_csr every call.
__device__ int    g_deg[NN];
__device__ int    g_off[NN + 1];
__device__ int    g_cur[NN];
__device__ int    g_bsum[SB];
__device__ int    g_ticket;
__device__ int    g_done;
__device__ int    g_csr_src[NE];
__device__ float  g_dinv[NN];
__device__ __half g_h1h[(size_t)NN * F1];   // x@W1; scaled by dinv in-place later
__device__ __half g_hs2h[(size_t)NN * F2];  // (h1@W2)*dinv, fp16

// ---------------------------------------------------------------------------
// Per-block dtype detect: int64 LE node ids < 2^31 -> ALL odd 32-bit words
// zero over the first 32 entries; impossible for int32 node ids here.
__device__ __forceinline__ int detect_is64_block(const unsigned int* uw,
                                                 int tid, int* shared_flag) {
    if (tid < 32) {
        unsigned v = uw[2 * tid + 1];
        unsigned any = __ballot_sync(0xffffffffu, v != 0u);
        if (tid == 0) *shared_flag = (any == 0u) ? 1 : 0;
    }
    __syncthreads();
    return *shared_flag;
}

// ---------------------------------------------------------------------------
// FUSED: blocks [0, PB) -> edge-degree histogram (4 edges/thread);
// blocks [PB, PB+GB1) -> raw gemm1 (h1 = x @ W1, fp32 math, fp16 store).
__global__ void fused_prep_gemm1(const float* __restrict__ x,
                                 const float* __restrict__ W,
                                 const int* __restrict__ w) {
    constexpr int K = 64, ROWS = 32, XP = K + 4, FOUT = F1;
    constexpr int NT = 128;
    __shared__ float xs[ROWS][XP];
    __shared__ float ws[K][FOUT];

    int tid = threadIdx.x;
    if (blockIdx.x < PB) {
        __shared__ int s_is64;
        int is64 = detect_is64_block((const unsigned int*)w, tid, &s_is64);
        int base = blockIdx.x * 512;
#pragma unroll
        for (int r = 0; r < 4; r++) {
            int e = base + r * 128 + tid;
            int d = is64 ? w[2 * (NE + e)] : w[NE + e];
            atomicAdd(&g_deg[d], 1);
        }
        return;
    }

    // ---- gemm phase: 32 rows, 4x4 micro-tile ----
    int row0 = (blockIdx.x - PB) * ROWS;
    for (int f4 = tid; f4 < ROWS * K / 4; f4 += NT) {
        int r = f4 >> 4, kc = f4 & 15;
        float4 v = ((const float4*)(x + (size_t)(row0 + r) * K))[kc];
        *(float4*)&xs[r][kc * 4] = v;
    }
    for (int f4 = tid; f4 < K * FOUT / 4; f4 += NT)
        ((float4*)ws)[f4] = ((const float4*)W)[f4];
    __syncthreads();

    int j = tid % 16;
    int i = tid / 16;
    float acc[4][4] = {};
#pragma unroll 8
    for (int k = 0; k < K; k++) {
        float av[4];
#pragma unroll
        for (int r = 0; r < 4; r++) av[r] = xs[i * 4 + r][k];
        float4 b = *(const float4*)&ws[k][j * 4];
#pragma unroll
        for (int r = 0; r < 4; r++) {
            acc[r][0] = fmaf(av[r], b.x, acc[r][0]);
            acc[r][1] = fmaf(av[r], b.y, acc[r][1]);
            acc[r][2] = fmaf(av[r], b.z, acc[r][2]);
            acc[r][3] = fmaf(av[r], b.w, acc[r][3]);
        }
    }
#pragma unroll
    for (int r = 0; r < 4; r++) {
        int row = row0 + i * 4 + r;
        __half2 p0 = __float22half2_rn(make_float2(acc[r][0], acc[r][1]));
        __half2 p1 = __float22half2_rn(make_float2(acc[r][2], acc[r][3]));
        __half2 pk[2] = {p0, p1};
        *(uint2*)&g_h1h[(size_t)row * FOUT + j * 4] = *(uint2*)pk;
    }
}

// ---------------------------------------------------------------------------
// Single-kernel exclusive scan of g_deg -> g_off/g_cur + dinv.
// 98 blocks x 1024 (<=1 block/SM -> all resident; spin is safe).
__global__ void scan_all() {
    int i = blockIdx.x * 1024 + threadIdx.x;
    int v = (i < NN) ? g_deg[i] : 0;
    int lane = threadIdx.x & 31, wid = threadIdx.x >> 5;

    int x = v;
#pragma unroll
    for (int o = 1; o < 32; o <<= 1) {
        int y = __shfl_up_sync(0xffffffffu, x, o);
        if (lane >= o) x += y;
    }
    __shared__ int ws[32];
    if (lane == 31) ws[wid] = x;
    __syncthreads();
    if (wid == 0) {
        int y = ws[lane];
        int s = y;
#pragma unroll
        for (int o = 1; o < 32; o <<= 1) {
            int z = __shfl_up_sync(0xffffffffu, s, o);
            if (lane >= o) s += z;
        }
        ws[lane] = s - y;  // exclusive warp offsets
    }
    __syncthreads();
    int xin = x + ws[wid];
    __shared__ int s_total;
    if (threadIdx.x == 1023) s_total = xin;
    __syncthreads();

    if (threadIdx.x == 0) {
        g_bsum[blockIdx.x] = s_total;
        __threadfence();
        int t = atomicAdd(&g_ticket, 1);
        if (t == SB - 1) {
            int r = 0;
            for (int k = 0; k < SB; k++) {
                int bv = g_bsum[k];
                g_bsum[k] = r;
                r += bv;
            }
            __threadfence();
            atomicExch(&g_ticket, 2 * SB);  // release
        }
        while (((volatile int*)&g_ticket)[0] != 2 * SB) {}
        __threadfence();  // acquire
    }
    __syncthreads();

    int off = g_bsum[blockIdx.x] + xin - v;
    if (i < NN) {
        g_off[i] = off;
        g_cur[i] = off;
        g_dinv[i] = rsqrtf((float)v + 2.0f);  // improved self-loops: +2
        if (i == NN - 1) g_off[NN] = off + v;
    }

    __syncthreads();
    if (threadIdx.x == 0) {
        int d2 = atomicAdd(&g_done, 1);
        if (d2 == SB - 1) {
            g_ticket = 0;
            g_done = 0;
        }
    }
}

// ---------------------------------------------------------------------------
// FUSED: blocks [0, FB) -> CSR fill (dtype-aware) + re-zero g_deg;
// blocks [FB, FB+SCB) -> scale h1h in-place by dinv[row] (fp32 math).
// Each scale thread handles 4 consecutive half2 (16B, row-aligned: 32 h2/row).
__global__ void fill_csr_scale(const int* __restrict__ w) {
    int tid = threadIdx.x;
    if (blockIdx.x >= FB) {
        int h2i = ((blockIdx.x - FB) * 256 + tid) * 4;   // half2 index
        int row = h2i >> 5;
        float dv = g_dinv[row];
        uint2* p = (uint2*)&g_h1h[(size_t)h2i * 2];
        uint2 v0 = p[0], v1 = p[1];
        __half2* h = (__half2*)&v0;
        __half2* h2 = (__half2*)&v1;
#pragma unroll
        for (int k = 0; k < 2; k++) {
            float2 f = __half22float2(h[k]);
            h[k] = __float22half2_rn(make_float2(f.x * dv, f.y * dv));
            float2 g = __half22float2(h2[k]);
            h2[k] = __float22half2_rn(make_float2(g.x * dv, g.y * dv));
        }
        p[0] = v0;
        p[1] = v1;
        return;
    }
    __shared__ int s_is64;
    int is64 = detect_is64_block((const unsigned int*)w, tid, &s_is64);
    int e = blockIdx.x * 256 + tid;
    if (e >= NE) return;
    if (e < NN) g_deg[e] = 0;
    int s, d;
    if (is64) {
        s = w[2 * e];
        d = w[2 * (NE + e)];
    } else {
        s = w[e];
        d = w[NE + e];
    }
    int pos = atomicAdd(&g_cur[d], 1);
    g_csr_src[pos] = s;
}

// ---------------------------------------------------------------------------
// Pull aggregation layer 1. One warp per dst node; TWO edges in flight via
// 16-lane half-warps. hs1 rows are PRE-SCALED by dinv[src] (fp16, 128B/row);
// lane l of group g owns features [4l, 4l+4) as a uint2 (half4) gather.
// out = relu(dv*(sum + 2*hs_self) + b) -> feature_map (fp32).
__global__ void agg1(const float* __restrict__ b, float* __restrict__ feat) {
    int warp = (blockIdx.x * 256 + threadIdx.x) >> 5;
    int lane = threadIdx.x & 31;
    if (warp >= NN) return;
    int g = lane >> 4, l = lane & 15;
    int beg = g_off[warp], end = g_off[warp + 1];
    const uint2* __restrict__ hs = (const uint2*)g_h1h;  // 16 uint2 per row
    const int* __restrict__ csr = g_csr_src;

    float a0 = 0.f, a1 = 0.f, a2 = 0.f, a3 = 0.f;
    int i = beg + g;
    // unroll x2: this half-warp handles edges i, i+2 (stride 2 per group).
    for (; i + 2 < end; i += 4) {
        int s0 = csr[i];
        int s1 = csr[i + 2];
        uint2 v0 = hs[s0 * 16 + l];
        uint2 v1 = hs[s1 * 16 + l];
        float2 f00 = __half22float2(*(__half2*)&v0.x);
        float2 f01 = __half22float2(*(__half2*)&v0.y);
        float2 f10 = __half22float2(*(__half2*)&v1.x);
        float2 f11 = __half22float2(*(__half2*)&v1.y);
        a0 += f00.x + f10.x;
        a1 += f00.y + f10.y;
        a2 += f01.x + f11.x;
        a3 += f01.y + f11.y;
    }
    if (i < end) {
        int s0 = csr[i];
        uint2 v0 = hs[s0 * 16 + l];
        float2 f00 = __half22float2(*(__half2*)&v0.x);
        float2 f01 = __half22float2(*(__half2*)&v0.y);
        a0 += f00.x;
        a1 += f00.y;
        a2 += f01.x;
        a3 += f01.y;
    }
    // combine the two half-warps (same features, disjoint edges).
    a0 += __shfl_xor_sync(0xffffffffu, a0, 16);
    a1 += __shfl_xor_sync(0xffffffffu, a1, 16);
    a2 += __shfl_xor_sync(0xffffffffu, a2, 16);
    a3 += __shfl_xor_sync(0xffffffffu, a3, 16);

    if (g == 0) {
        float dv = g_dinv[warp];
        uint2 hv = hs[warp * 16 + l];
        float2 h0 = __half22float2(*(__half2*)&hv.x);
        float2 h1 = __half22float2(*(__half2*)&hv.y);
        float4 bb = ((const float4*)b)[l];
        float4 o;
        o.x = fmaxf(fmaf(dv, fmaf(2.f, h0.x, a0), bb.x), 0.f);
        o.y = fmaxf(fmaf(dv, fmaf(2.f, h0.y, a1), bb.y), 0.f);
        o.z = fmaxf(fmaf(dv, fmaf(2.f, h1.x, a2), bb.z), 0.f);
        o.w = fmaxf(fmaf(dv, fmaf(2.f, h1.y, a3), bb.w), 0.f);
        ((float4*)feat)[warp * 16 + l] = o;
    }
}

// ---------------------------------------------------------------------------
// GEMM layer 2: g_hs2h[row,:] = half((feat[row,:] @ W) * dinv[row]).
__global__ void gemm2_scale(const float* __restrict__ x,
                            const float* __restrict__ W) {
    constexpr int K = 64, ROWS = 32, XP = K + 4, FOUT = F2;
    constexpr int TJ = FOUT / 4;          // 8
    constexpr int NT = (ROWS / 4) * TJ;   // 64 threads
    __shared__ float xs[ROWS][XP];
    __shared__ float ws[K][FOUT];

    int tid = threadIdx.x;
    int row0 = blockIdx.x * ROWS;

    for (int f4 = tid; f4 < ROWS * K / 4; f4 += NT) {
        int r = f4 >> 4, kc = f4 & 15;
        float4 v = ((const float4*)(x + (size_t)(row0 + r) * K))[kc];
        *(float4*)&xs[r][kc * 4] = v;
    }
    for (int f4 = tid; f4 < K * FOUT / 4; f4 += NT)
        ((float4*)ws)[f4] = ((const float4*)W)[f4];
    __syncthreads();

    int j = tid % TJ;
    int i = tid / TJ;
    float acc[4][4] = {};
#pragma unroll 8
    for (int k = 0; k < K; k++) {
        float av[4];
#pragma unroll
        for (int r = 0; r < 4; r++) av[r] = xs[i * 4 + r][k];
        float4 b = *(const float4*)&ws[k][j * 4];
#pragma unroll
        for (int r = 0; r < 4; r++) {
            acc[r][0] = fmaf(av[r], b.x, acc[r][0]);
            acc[r][1] = fmaf(av[r], b.y, acc[r][1]);
            acc[r][2] = fmaf(av[r], b.z, acc[r][2]);
            acc[r][3] = fmaf(av[r], b.w, acc[r][3]);
        }
    }
#pragma unroll
    for (int r = 0; r < 4; r++) {
        int row = row0 + i * 4 + r;
        float dv = g_dinv[row];
        __half2 p0 = __float22half2_rn(make_float2(acc[r][0] * dv, acc[r][1] * dv));
        __half2 p1 = __float22half2_rn(make_float2(acc[r][2] * dv, acc[r][3] * dv));
        __half2 pk[2] = {p0, p1};
        *(uint2*)&g_hs2h[(size_t)row * FOUT + j * 4] = *(uint2*)pk;
    }
}

// ---------------------------------------------------------------------------
// Layer-2 aggregation: same 2-edges-per-warp scheme. Row = 32 half = 16 half2;
// lane l owns features [2l, 2l+2) as one half2 (4B).
__global__ void agg2(const float* __restrict__ b, float* __restrict__ out) {
    int warp = (blockIdx.x * 256 + threadIdx.x) >> 5;
    int lane = threadIdx.x & 31;
    if (warp >= NN) return;
    int g = lane >> 4, l = lane & 15;
    int beg = g_off[warp], end = g_off[warp + 1];
    const __half2* __restrict__ hs = (const __half2*)g_hs2h;  // 16 h2 per row
    const int* __restrict__ csr = g_csr_src;

    float a0 = 0.f, a1 = 0.f;
    int i = beg + g;
    for (; i + 2 < end; i += 4) {
        int s0 = csr[i];
        int s1 = csr[i + 2];
        float2 f0 = __half22float2(hs[s0 * 16 + l]);
        float2 f1 = __half22float2(hs[s1 * 16 + l]);
        a0 += f0.x + f1.x;
        a1 += f0.y + f1.y;
    }
    if (i < end) {
        float2 f0 = __half22float2(hs[csr[i] * 16 + l]);
        a0 += f0.x;
        a1 += f0.y;
    }
    a0 += __shfl_xor_sync(0xffffffffu, a0, 16);
    a1 += __shfl_xor_sync(0xffffffffu, a1, 16);

    if (g == 0) {
        float dv = g_dinv[warp];
        float2 h = __half22float2(hs[warp * 16 + l]);
        float2 bb = ((const float2*)b)[l];
        float2 o;
        o.x = fmaf(dv, fmaf(2.f, h.x, a0), bb.x);
        o.y = fmaf(dv, fmaf(2.f, h.y, a1), bb.y);
        ((float2*)out)[warp * 16 + l] = o;
    }
}

// ---------------------------------------------------------------------------
extern "C" void kernel_launch(void* const* d_in, const int* in_sizes, int n_in,
                              void* d_out, int out_size) {
    const float* x  = (const float*)d_in[0];
    const int*   ei = (const int*)d_in[1];
    const float* W1 = (const float*)d_in[2];
    const float* b1 = (const float*)d_in[3];
    const float* W2 = (const float*)d_in[4];
    const float* b2 = (const float*)d_in[5];

    float* out  = (float*)d_out;              // [N, 32]
    float* feat = out + (size_t)NN * F2;      // [N, 64] feature_map

    fused_prep_gemm1<<<PB + GB1, 128>>>(x, W1, ei);
    scan_all<<<SB, 1024>>>();
    fill_csr_scale<<<FB + SCB, 256>>>(ei);
    agg1<<<(NN * 32 + 255) / 256, 256>>>(b1, feat);
    gemm2_scale<<<NN / 32, 64>>>(feat, W2);
    agg2<<<(NN * 32 + 255) / 256, 256>>>(b2, out);
}

// round 14
// speedup vs baseline: 1.1255x; 1.0112x over previous
#include <cuda_runtime.h>
#include <cuda_fp16.h>

// Problem constants (fixed by the reference).
constexpr int NN = 100000;   // nodes
constexpr int NE = 1600000;  // edges
constexpr int F1 = 64;       // layer-1 out features (== Fin)
constexpr int F2 = 32;       // layer-2 out features
constexpr int SB = (NN + 1023) / 1024;   // 98 scan blocks (1024 threads)
constexpr int PB = NE / 512;             // 3125 prep blocks (128 thr x 4 edges)
constexpr int GB1 = NN / 32;             // 3125 gemm blocks in fused kernel
constexpr int FB = (NE + 255) / 256;     // 6250 csr-fill blocks
constexpr int SCB = (NN * F1 / 2) / (256 * 4);  // 3125 h1-scale blocks

// Scratch (device globals — referenced ONLY inside device code; passing the
// symbol as a kernel arg from host passes the host shadow address on GB300
// ATS and silently corrupts results — R5/R6 bug).
// g_deg is zero at program load and re-zeroed by fill_csr every call.
__device__ int    g_deg[NN];
__device__ int    g_off[NN + 1];
__device__ int    g_cur[NN];
__device__ int    g_bsum[SB];
__device__ int    g_ticket;
__device__ int    g_done;
__device__ int    g_csr_src[NE];
__device__ float  g_dinv[NN];
__device__ __half g_h1h[(size_t)NN * F1];   // x@W1; scaled by dinv in-place later
__device__ __half g_hs2h[(size_t)NN * F2];  // (h1@W2)*dinv, fp16

// ---------------------------------------------------------------------------
// Per-block dtype detect: int64 LE node ids < 2^31 -> ALL odd 32-bit words
// zero over the first 32 entries; impossible for int32 node ids here.
__device__ __forceinline__ int detect_is64_block(const unsigned int* uw,
                                                 int tid, int* shared_flag) {
    if (tid < 32) {
        unsigned v = uw[2 * tid + 1];
        unsigned any = __ballot_sync(0xffffffffu, v != 0u);
        if (tid == 0) *shared_flag = (any == 0u) ? 1 : 0;
    }
    __syncthreads();
    return *shared_flag;
}

// ---------------------------------------------------------------------------
// FUSED: blocks [0, PB) -> edge-degree histogram (4 edges/thread);
// blocks [PB, PB+GB1) -> raw gemm1 (h1 = x @ W1, fp32 math, fp16 store).
__global__ void fused_prep_gemm1(const float* __restrict__ x,
                                 const float* __restrict__ W,
                                 const int* __restrict__ w) {
    constexpr int K = 64, ROWS = 32, XP = K + 4, FOUT = F1;
    constexpr int NT = 128;
    __shared__ float xs[ROWS][XP];
    __shared__ float ws[K][FOUT];

    int tid = threadIdx.x;
    if (blockIdx.x < PB) {
        __shared__ int s_is64;
        int is64 = detect_is64_block((const unsigned int*)w, tid, &s_is64);
        int base = blockIdx.x * 512;
#pragma unroll
        for (int r = 0; r < 4; r++) {
            int e = base + r * 128 + tid;
            int d = is64 ? w[2 * (NE + e)] : w[NE + e];
            atomicAdd(&g_deg[d], 1);
        }
        return;
    }

    // ---- gemm phase: 32 rows, 4x4 micro-tile ----
    int row0 = (blockIdx.x - PB) * ROWS;
    for (int f4 = tid; f4 < ROWS * K / 4; f4 += NT) {
        int r = f4 >> 4, kc = f4 & 15;
        float4 v = ((const float4*)(x + (size_t)(row0 + r) * K))[kc];
        *(float4*)&xs[r][kc * 4] = v;
    }
    for (int f4 = tid; f4 < K * FOUT / 4; f4 += NT)
        ((float4*)ws)[f4] = ((const float4*)W)[f4];
    __syncthreads();

    int j = tid % 16;
    int i = tid / 16;
    float acc[4][4] = {};
#pragma unroll 8
    for (int k = 0; k < K; k++) {
        float av[4];
#pragma unroll
        for (int r = 0; r < 4; r++) av[r] = xs[i * 4 + r][k];
        float4 b = *(const float4*)&ws[k][j * 4];
#pragma unroll
        for (int r = 0; r < 4; r++) {
            acc[r][0] = fmaf(av[r], b.x, acc[r][0]);
            acc[r][1] = fmaf(av[r], b.y, acc[r][1]);
            acc[r][2] = fmaf(av[r], b.z, acc[r][2]);
            acc[r][3] = fmaf(av[r], b.w, acc[r][3]);
        }
    }
#pragma unroll
    for (int r = 0; r < 4; r++) {
        int row = row0 + i * 4 + r;
        __half2 p0 = __float22half2_rn(make_float2(acc[r][0], acc[r][1]));
        __half2 p1 = __float22half2_rn(make_float2(acc[r][2], acc[r][3]));
        __half2 pk[2] = {p0, p1};
        *(uint2*)&g_h1h[(size_t)row * FOUT + j * 4] = *(uint2*)pk;
    }
}

// ---------------------------------------------------------------------------
// Single-kernel exclusive scan of g_deg -> g_off/g_cur + dinv.
// 98 blocks x 1024 (<=1 block/SM -> all resident; spin is safe).
__global__ void scan_all() {
    int i = blockIdx.x * 1024 + threadIdx.x;
    int v = (i < NN) ? g_deg[i] : 0;
    int lane = threadIdx.x & 31, wid = threadIdx.x >> 5;

    int x = v;
#pragma unroll
    for (int o = 1; o < 32; o <<= 1) {
        int y = __shfl_up_sync(0xffffffffu, x, o);
        if (lane >= o) x += y;
    }
    __shared__ int ws[32];
    if (lane == 31) ws[wid] = x;
    __syncthreads();
    if (wid == 0) {
        int y = ws[lane];
        int s = y;
#pragma unroll
        for (int o = 1; o < 32; o <<= 1) {
            int z = __shfl_up_sync(0xffffffffu, s, o);
            if (lane >= o) s += z;
        }
        ws[lane] = s - y;  // exclusive warp offsets
    }
    __syncthreads();
    int xin = x + ws[wid];
    __shared__ int s_total;
    if (threadIdx.x == 1023) s_total = xin;
    __syncthreads();

    if (threadIdx.x == 0) {
        g_bsum[blockIdx.x] = s_total;
        __threadfence();
        int t = atomicAdd(&g_ticket, 1);
        if (t == SB - 1) {
            int r = 0;
            for (int k = 0; k < SB; k++) {
                int bv = g_bsum[k];
                g_bsum[k] = r;
                r += bv;
            }
            __threadfence();
            atomicExch(&g_ticket, 2 * SB);  // release
        }
        while (((volatile int*)&g_ticket)[0] != 2 * SB) {}
        __threadfence();  // acquire
    }
    __syncthreads();

    int off = g_bsum[blockIdx.x] + xin - v;
    if (i < NN) {
        g_off[i] = off;
        g_cur[i] = off;
        g_dinv[i] = rsqrtf((float)v + 2.0f);  // improved self-loops: +2
        if (i == NN - 1) g_off[NN] = off + v;
    }

    __syncthreads();
    if (threadIdx.x == 0) {
        int d2 = atomicAdd(&g_done, 1);
        if (d2 == SB - 1) {
            g_ticket = 0;
            g_done = 0;
        }
    }
}

// ---------------------------------------------------------------------------
// FUSED: blocks [0, FB) -> CSR fill (dtype-aware) + re-zero g_deg;
// blocks [FB, FB+SCB) -> scale h1h in-place by dinv[row] (fp32 math).
// Each scale thread handles 4 consecutive half2 (16B, row-aligned: 32 h2/row).
__global__ void fill_csr_scale(const int* __restrict__ w) {
    int tid = threadIdx.x;
    if (blockIdx.x >= FB) {
        int h2i = ((blockIdx.x - FB) * 256 + tid) * 4;   // half2 index
        int row = h2i >> 5;
        float dv = g_dinv[row];
        uint2* p = (uint2*)&g_h1h[(size_t)h2i * 2];
        uint2 v0 = p[0], v1 = p[1];
        __half2* h = (__half2*)&v0;
        __half2* h2 = (__half2*)&v1;
#pragma unroll
        for (int k = 0; k < 2; k++) {
            float2 f = __half22float2(h[k]);
            h[k] = __float22half2_rn(make_float2(f.x * dv, f.y * dv));
            float2 g = __half22float2(h2[k]);
            h2[k] = __float22half2_rn(make_float2(g.x * dv, g.y * dv));
        }
        p[0] = v0;
        p[1] = v1;
        return;
    }
    __shared__ int s_is64;
    int is64 = detect_is64_block((const unsigned int*)w, tid, &s_is64);
    int e = blockIdx.x * 256 + tid;
    if (e >= NE) return;
    if (e < NN) g_deg[e] = 0;
    int s, d;
    if (is64) {
        s = w[2 * e];
        d = w[2 * (NE + e)];
    } else {
        s = w[e];
        d = w[NE + e];
    }
    int pos = atomicAdd(&g_cur[d], 1);
    g_csr_src[pos] = s;
}

// ---------------------------------------------------------------------------
// Pull aggregation layer 1. One warp per dst node; TWO edges in flight via
// 16-lane half-warps. hs1 rows are PRE-SCALED by dinv[src] (fp16, 128B/row);
// lane l of group g owns features [4l, 4l+4) as a uint2 (half4) gather.
// out = relu(dv*(sum + 2*hs_self) + b) -> feature_map (fp32).
__global__ void agg1(const float* __restrict__ b, float* __restrict__ feat) {
    int warp = (blockIdx.x * 256 + threadIdx.x) >> 5;
    int lane = threadIdx.x & 31;
    if (warp >= NN) return;
    int g = lane >> 4, l = lane & 15;
    int beg = g_off[warp], end = g_off[warp + 1];
    const uint2* __restrict__ hs = (const uint2*)g_h1h;  // 16 uint2 per row
    const int* __restrict__ csr = g_csr_src;

    float a0 = 0.f, a1 = 0.f, a2 = 0.f, a3 = 0.f;
    int i = beg + g;
    // unroll x2: this half-warp handles edges i, i+2 (stride 2 per group).
    for (; i + 2 < end; i += 4) {
        int s0 = csr[i];
        int s1 = csr[i + 2];
        uint2 v0 = hs[s0 * 16 + l];
        uint2 v1 = hs[s1 * 16 + l];
        float2 f00 = __half22float2(*(__half2*)&v0.x);
        float2 f01 = __half22float2(*(__half2*)&v0.y);
        float2 f10 = __half22float2(*(__half2*)&v1.x);
        float2 f11 = __half22float2(*(__half2*)&v1.y);
        a0 += f00.x + f10.x;
        a1 += f00.y + f10.y;
        a2 += f01.x + f11.x;
        a3 += f01.y + f11.y;
    }
    if (i < end) {
        int s0 = csr[i];
        uint2 v0 = hs[s0 * 16 + l];
        float2 f00 = __half22float2(*(__half2*)&v0.x);
        float2 f01 = __half22float2(*(__half2*)&v0.y);
        a0 += f00.x;
        a1 += f00.y;
        a2 += f01.x;
        a3 += f01.y;
    }
    // combine the two half-warps (same features, disjoint edges).
    a0 += __shfl_xor_sync(0xffffffffu, a0, 16);
    a1 += __shfl_xor_sync(0xffffffffu, a1, 16);
    a2 += __shfl_xor_sync(0xffffffffu, a2, 16);
    a3 += __shfl_xor_sync(0xffffffffu, a3, 16);

    if (g == 0) {
        float dv = g_dinv[warp];
        uint2 hv = hs[warp * 16 + l];
        float2 h0 = __half22float2(*(__half2*)&hv.x);
        float2 h1 = __half22float2(*(__half2*)&hv.y);
        float4 bb = ((const float4*)b)[l];
        float4 o;
        o.x = fmaxf(fmaf(dv, fmaf(2.f, h0.x, a0), bb.x), 0.f);
        o.y = fmaxf(fmaf(dv, fmaf(2.f, h0.y, a1), bb.y), 0.f);
        o.z = fmaxf(fmaf(dv, fmaf(2.f, h1.x, a2), bb.z), 0.f);
        o.w = fmaxf(fmaf(dv, fmaf(2.f, h1.y, a3), bb.w), 0.f);
        ((float4*)feat)[warp * 16 + l] = o;
    }
}

// ---------------------------------------------------------------------------
// GEMM layer 2: g_hs2h[row,:] = half((feat[row,:] @ W) * dinv[row]).
__global__ void gemm2_scale(const float* __restrict__ x,
                            const float* __restrict__ W) {
    constexpr int K = 64, ROWS = 32, XP = K + 4, FOUT = F2;
    constexpr int TJ = FOUT / 4;          // 8
    constexpr int NT = (ROWS / 4) * TJ;   // 64 threads
    __shared__ float xs[ROWS][XP];
    __shared__ float ws[K][FOUT];

    int tid = threadIdx.x;
    int row0 = blockIdx.x * ROWS;

    for (int f4 = tid; f4 < ROWS * K / 4; f4 += NT) {
        int r = f4 >> 4, kc = f4 & 15;
        float4 v = ((const float4*)(x + (size_t)(row0 + r) * K))[kc];
        *(float4*)&xs[r][kc * 4] = v;
    }
    for (int f4 = tid; f4 < K * FOUT / 4; f4 += NT)
        ((float4*)ws)[f4] = ((const float4*)W)[f4];
    __syncthreads();

    int j = tid % TJ;
    int i = tid / TJ;
    float acc[4][4] = {};
#pragma unroll 8
    for (int k = 0; k < K; k++) {
        float av[4];
#pragma unroll
        for (int r = 0; r < 4; r++) av[r] = xs[i * 4 + r][k];
        float4 b = *(const float4*)&ws[k][j * 4];
#pragma unroll
        for (int r = 0; r < 4; r++) {
            acc[r][0] = fmaf(av[r], b.x, acc[r][0]);
            acc[r][1] = fmaf(av[r], b.y, acc[r][1]);
            acc[r][2] = fmaf(av[r], b.z, acc[r][2]);
            acc[r][3] = fmaf(av[r], b.w, acc[r][3]);
        }
    }
#pragma unroll
    for (int r = 0; r < 4; r++) {
        int row = row0 + i * 4 + r;
        float dv = g_dinv[row];
        __half2 p0 = __float22half2_rn(make_float2(acc[r][0] * dv, acc[r][1] * dv));
        __half2 p1 = __float22half2_rn(make_float2(acc[r][2] * dv, acc[r][3] * dv));
        __half2 pk[2] = {p0, p1};
        *(uint2*)&g_hs2h[(size_t)row * FOUT + j * 4] = *(uint2*)pk;
    }
}

// ---------------------------------------------------------------------------
// Layer-2 aggregation: same 2-edges-per-warp scheme. Row = 32 half = 16 half2;
// lane l owns features [2l, 2l+2) as one half2 (4B).
__global__ void agg2(const float* __restrict__ b, float* __restrict__ out) {
    int warp = (blockIdx.x * 256 + threadIdx.x) >> 5;
    int lane = threadIdx.x & 31;
    if (warp >= NN) return;
    int g = lane >> 4, l = lane & 15;
    int beg = g_off[warp], end = g_off[warp + 1];
    const __half2* __restrict__ hs = (const __half2*)g_hs2h;  // 16 h2 per row
    const int* __restrict__ csr = g_csr_src;

    float a0 = 0.f, a1 = 0.f;
    int i = beg + g;
    for (; i + 2 < end; i += 4) {
        int s0 = csr[i];
        int s1 = csr[i + 2];
        float2 f0 = __half22float2(hs[s0 * 16 + l]);
        float2 f1 = __half22float2(hs[s1 * 16 + l]);
        a0 += f0.x + f1.x;
        a1 += f0.y + f1.y;
    }
    if (i < end) {
        float2 f0 = __half22float2(hs[csr[i] * 16 + l]);
        a0 += f0.x;
        a1 += f0.y;
    }
    a0 += __shfl_xor_sync(0xffffffffu, a0, 16);
    a1 += __shfl_xor_sync(0xffffffffu, a1, 16);

    if (g == 0) {
        float dv = g_dinv[warp];
        float2 h = __half22float2(hs[warp * 16 + l]);
        float2 bb = ((const float2*)b)[l];
        float2 o;
        o.x = fmaf(dv, fmaf(2.f, h.x, a0), bb.x);
        o.y = fmaf(dv, fmaf(2.f, h.y, a1), bb.y);
        ((float2*)out)[warp * 16 + l] = o;
    }
}

// ---------------------------------------------------------------------------
extern "C" void kernel_launch(void* const* d_in, const int* in_sizes, int n_in,
                              void* d_out, int out_size) {
    const float* x  = (const float*)d_in[0];
    const int*   ei = (const int*)d_in[1];
    const float* W1 = (const float*)d_in[2];
    const float* b1 = (const float*)d_in[3];
    const float* W2 = (const float*)d_in[4];
    const float* b2 = (const float*)d_in[5];

    float* out  = (float*)d_out;              // [N, 32]
    float* feat = out + (size_t)NN * F2;      // [N, 64] feature_map

    fused_prep_gemm1<<<PB + GB1, 128>>>(x, W1, ei);
    scan_all<<<SB, 1024>>>();
    fill_csr_scale<<<FB + SCB, 256>>>(ei);
    agg1<<<(NN * 32 + 255) / 256, 256>>>(b1, feat);
    gemm2_scale<<<NN / 32, 64>>>(feat, W2);
    agg2<<<(NN * 32 + 255) / 256, 256>>>(b2, out);
}